// round 2
// baseline (speedup 1.0000x reference)
#include <cuda_runtime.h>
#include <cstdint>

typedef unsigned long long ull;
#define DEV __device__ __forceinline__

DEV ull pk2(float lo, float hi){
    unsigned a = __float_as_uint(lo), b = __float_as_uint(hi);
    ull r; asm("mov.b64 %0, {%1, %2};" : "=l"(r) : "r"(a), "r"(b)); return r;
}
DEV void fma2(ull& d, ull a, ull b){
    asm("fma.rn.f32x2 %0, %1, %2, %0;" : "+l"(d) : "l"(a), "l"(b));
}
DEV float2 up2(ull v){
    unsigned a, b; asm("mov.b64 {%0, %1}, %2;" : "=r"(a), "=r"(b) : "l"(v));
    return make_float2(__uint_as_float(a), __uint_as_float(b));
}
DEV float sigm(float x){ return 1.0f/(1.0f+__expf(-x)); }
DEV float ftanh(float x){ return 1.0f - 2.0f/(__expf(2.0f*x)+1.0f); }

// ---------------- problem dims ----------------
// B=64, S=50, T=50, U=1024, E=256, VT=16000, G3=3072

// ---------------- scratch layout (floats) ----------------
constexpr long O_ENCGI = 0;                        // 3200 x 3072  enc x@Wx+b0, row=b*50+t
constexpr long O_DEMB  = O_ENCGI + 3200L*3072;     // 3136 x 3072  dec emb@Wx[U:]+b0, row=t*64+b
constexpr long O_EO    = O_DEMB  + 3136L*3072;     // enc_out (b,s,u)
constexpr long O_KEYS  = O_EO    + 3276800L;       // keys (b,s,u)
constexpr long O_PART  = O_KEYS  + 3276800L;       // split-K partials 4 x 64 x 3072
constexpr long O_QPART = O_PART  + 786432L;        // split-K partials 4 x 64 x 1024
constexpr long O_H     = O_QPART + 262144L;        // h (64x1024)
constexpr long O_CTX   = O_H     + 65536L;         // ctx (64x1024)
constexpr long O_HALL  = O_CTX   + 65536L;         // all decoder h_new 3136 x 1024
constexpr long O_LOG   = O_HALL  + 3211264L;       // logits 3136 x 16000
constexpr long O_NLL   = O_LOG   + 50176000L;      // per-row masked nll/64 (3136)
constexpr long SCRATCH_TOTAL = O_NLL + 3200L;

__device__ __align__(16) float g_scratch[SCRATCH_TOTAL];
__device__ int g_didx[3136];

// ---------------- setup ----------------
__global__ void setup_didx(const int* __restrict__ targ, int* __restrict__ gd){
    int i = blockIdx.x*256 + threadIdx.x;
    if (i < 3136){ int t = i >> 6, b = i & 63; gd[i] = targ[b*50 + t]; }
}
__global__ void copy_vec(float* __restrict__ dst, const float* __restrict__ src){
    int i = blockIdx.x*256 + threadIdx.x;
    dst[i] = src[i];
}

// ---------------- 64x64-tile GEMM: C = gather(A)@B + bias ----------------
// M,N multiples of 64; K multiple of 16. f32x2 microkernel, 256 threads.
__global__ __launch_bounds__(256) void gemm_tile64(
    const float* __restrict__ A, int lda, const int* __restrict__ gidx,
    const float* __restrict__ Bm, const float* __restrict__ bias,
    float* __restrict__ C, int N, int K)
{
    __shared__ __align__(16) ull   As2[16][68];   // duplicated A, 544B rows (16B-aligned), pad vs conflicts
    __shared__ __align__(16) float Bs[16][64];
    const int tid = threadIdx.x;
    const int tx = tid & 15, ty = tid >> 4;
    const int row0 = blockIdx.y << 6, col0 = blockIdx.x << 6;

    ull acc[4][2];
    #pragma unroll
    for (int i=0;i<4;i++){ acc[i][0]=0ull; acc[i][1]=0ull; }

    const int ra = tid >> 2, qa = tid & 3;     // A loader: 64 rows x 4x(float4)
    long arow = gidx ? (long)gidx[row0 + ra] : (long)(row0 + ra);
    const int kb = tid >> 4, c4 = tid & 15;    // B loader: 16 k-rows x 16x(float4)

    for (int k0 = 0; k0 < K; k0 += 16){
        float4 av = *reinterpret_cast<const float4*>(&A[arow*lda + k0 + (qa<<2)]);
        int kk = qa << 2;
        As2[kk+0][ra] = pk2(av.x, av.x);
        As2[kk+1][ra] = pk2(av.y, av.y);
        As2[kk+2][ra] = pk2(av.z, av.z);
        As2[kk+3][ra] = pk2(av.w, av.w);
        *reinterpret_cast<float4*>(&Bs[kb][c4<<2]) =
            *reinterpret_cast<const float4*>(&Bm[(long)(k0+kb)*N + col0 + (c4<<2)]);
        __syncthreads();
        #pragma unroll
        for (int k=0;k<16;k++){
            ulonglong2 a01 = *reinterpret_cast<const ulonglong2*>(&As2[k][ty<<2]);
            ulonglong2 a23 = *reinterpret_cast<const ulonglong2*>(&As2[k][(ty<<2)+2]);
            ulonglong2 bb  = *reinterpret_cast<const ulonglong2*>(&Bs[k][tx<<2]);
            fma2(acc[0][0], a01.x, bb.x); fma2(acc[0][1], a01.x, bb.y);
            fma2(acc[1][0], a01.y, bb.x); fma2(acc[1][1], a01.y, bb.y);
            fma2(acc[2][0], a23.x, bb.x); fma2(acc[2][1], a23.x, bb.y);
            fma2(acc[3][0], a23.y, bb.x); fma2(acc[3][1], a23.y, bb.y);
        }
        __syncthreads();
    }
    const int c0 = col0 + (tx<<2);
    float4 bv = make_float4(0.f,0.f,0.f,0.f);
    if (bias) bv = *reinterpret_cast<const float4*>(&bias[c0]);
    #pragma unroll
    for (int i=0;i<4;i++){
        int r = row0 + (ty<<2) + i;
        float2 p0 = up2(acc[i][0]), p1 = up2(acc[i][1]);
        float4 o = make_float4(p0.x+bv.x, p0.y+bv.y, p1.x+bv.z, p1.y+bv.w);
        *reinterpret_cast<float4*>(&C[(long)r*N + c0]) = o;
    }
}

// ---------------- skinny GEMM: M=64, BN=32, split-K into ksplit partials ----------------
// grid (N/32, ksplit); partial z written to C + z*64*N. A is 64 x Ktot, row stride Ktot.
__global__ __launch_bounds__(256) void gemm_skinny(
    const float* __restrict__ A, const float* __restrict__ Bm,
    float* __restrict__ C, int N, int Ktot, int ksplit)
{
    __shared__ __align__(16) ull   As2[16][68];
    __shared__ __align__(16) float Bs[16][32];
    const int tid = threadIdx.x;
    const int tx = tid & 7, ty = tid >> 3;        // tx: 4 cols (2 f32x2), ty: 2 rows
    const int col0 = blockIdx.x << 5;
    const int Ks = Ktot / ksplit;
    const int kbeg = blockIdx.y * Ks;

    ull acc[2][2];
    acc[0][0]=0ull; acc[0][1]=0ull; acc[1][0]=0ull; acc[1][1]=0ull;

    const int ra = tid >> 2, qa = tid & 3;
    const int kb = tid >> 3, c4 = tid & 7;        // first 128 threads load B

    for (int k0 = kbeg; k0 < kbeg + Ks; k0 += 16){
        float4 av = *reinterpret_cast<const float4*>(&A[ra*Ktot + k0 + (qa<<2)]);
        int kk = qa << 2;
        As2[kk+0][ra] = pk2(av.x, av.x);
        As2[kk+1][ra] = pk2(av.y, av.y);
        As2[kk+2][ra] = pk2(av.z, av.z);
        As2[kk+3][ra] = pk2(av.w, av.w);
        if (tid < 128){
            *reinterpret_cast<float4*>(&Bs[kb][c4<<2]) =
                *reinterpret_cast<const float4*>(&Bm[(long)(k0+kb)*N + col0 + (c4<<2)]);
        }
        __syncthreads();
        #pragma unroll
        for (int k=0;k<16;k++){
            ulonglong2 a = *reinterpret_cast<const ulonglong2*>(&As2[k][ty<<1]);
            ulonglong2 b = *reinterpret_cast<const ulonglong2*>(&Bs[k][tx<<2]);
            fma2(acc[0][0], a.x, b.x); fma2(acc[0][1], a.x, b.y);
            fma2(acc[1][0], a.y, b.x); fma2(acc[1][1], a.y, b.y);
        }
        __syncthreads();
    }
    float* Cout = C + (long)blockIdx.y * 64 * N;
    const int c0 = col0 + (tx<<2);
    #pragma unroll
    for (int i=0;i<2;i++){
        int r = (ty<<1) + i;
        float2 p0 = up2(acc[i][0]), p1 = up2(acc[i][1]);
        float4 o = make_float4(p0.x, p0.y, p1.x, p1.y);
        *reinterpret_cast<float4*>(&Cout[(long)r*N + c0]) = o;
    }
}

// ---------------- encoder GRU combine ----------------
__global__ __launch_bounds__(256) void enc_combine(
    int t, const float* __restrict__ encgi, const float* __restrict__ part,
    float* __restrict__ h, float* __restrict__ eo, const float* __restrict__ encb)
{
    const int PS = 64*3072;
    int i = blockIdx.x*256 + threadIdx.x;      // 0..65535
    int b = i >> 10, u = i & 1023;
    long gb = (long)(b*50 + t)*3072;
    long p  = (long)b*3072;
    float giz = encgi[gb + u];
    float gir = encgi[gb + 1024 + u];
    float gih = encgi[gb + 2048 + u];
    float ghz = part[p+u]      + part[PS+p+u]      + part[2*PS+p+u]      + part[3*PS+p+u]      + encb[3072 + u];
    float ghr = part[p+1024+u] + part[PS+p+1024+u] + part[2*PS+p+1024+u] + part[3*PS+p+1024+u] + encb[3072 + 1024 + u];
    float ghh = part[p+2048+u] + part[PS+p+2048+u] + part[2*PS+p+2048+u] + part[3*PS+p+2048+u] + encb[3072 + 2048 + u];
    float z = sigm(giz + ghz);
    float r = sigm(gir + ghr);
    float hc = ftanh(gih + r*ghh);
    float hn = z*h[i] + (1.0f - z)*hc;
    h[i] = hn;
    eo[(long)(b*50 + t)*1024 + u] = hn;
}

// ---------------- decoder GRU combine (h input == 0 -> gh = dec_b[1]) ----------------
__global__ __launch_bounds__(256) void dec_combine(
    int t, const float* __restrict__ dembgi, const float* __restrict__ part,
    float* __restrict__ h, float* __restrict__ hall, const float* __restrict__ decb)
{
    const int PS = 64*3072;
    int i = blockIdx.x*256 + threadIdx.x;
    int b = i >> 10, u = i & 1023;
    long db = (long)(t*64 + b)*3072;
    long p  = (long)b*3072;
    float giz = dembgi[db + u]        + part[p+u]      + part[PS+p+u]      + part[2*PS+p+u]      + part[3*PS+p+u];
    float gir = dembgi[db + 1024 + u] + part[p+1024+u] + part[PS+p+1024+u] + part[2*PS+p+1024+u] + part[3*PS+p+1024+u];
    float gih = dembgi[db + 2048 + u] + part[p+2048+u] + part[PS+p+2048+u] + part[2*PS+p+2048+u] + part[3*PS+p+2048+u];
    float z = sigm(giz + decb[3072 + u]);
    float r = sigm(gir + decb[3072 + 1024 + u]);
    float hc = ftanh(gih + r*decb[3072 + 2048 + u]);
    float hn = (1.0f - z)*hc;
    h[i] = hn;
    hall[(long)(t*64 + b)*1024 + u] = hn;
}

// ---------------- attention: q-sum, scores, softmax, ctx (one block per batch row) ----------------
__global__ __launch_bounds__(512) void attention(
    const float* __restrict__ qpart, const float* __restrict__ keys,
    const float* __restrict__ eo, float* __restrict__ ctx,
    const float* __restrict__ b1, const float* __restrict__ V, const float* __restrict__ bV)
{
    __shared__ float qs[1024];
    __shared__ float sc[64];
    const int b = blockIdx.x;
    const int tid = threadIdx.x;
    const int QP = 64*1024;
    for (int u = tid; u < 1024; u += 512)
        qs[u] = qpart[b*1024+u] + qpart[QP + b*1024+u] + qpart[2*QP + b*1024+u] + qpart[3*QP + b*1024+u] + b1[u];
    __syncthreads();

    const int w = tid >> 5, lane = tid & 31;
    for (int s = w; s < 50; s += 16){
        const float* kr = keys + (long)(b*50 + s)*1024;
        float acc = 0.f;
        for (int u = lane; u < 1024; u += 32)
            acc += V[u] * ftanh(qs[u] + kr[u]);
        #pragma unroll
        for (int o = 16; o; o >>= 1) acc += __shfl_xor_sync(0xffffffffu, acc, o);
        if (lane == 0) sc[s] = acc + bV[0];
    }
    __syncthreads();

    if (w == 0){
        float v0 = sc[lane];
        bool has1 = (lane + 32) < 50;
        float v1 = has1 ? sc[lane + 32] : -1e30f;
        float m = fmaxf(v0, v1);
        #pragma unroll
        for (int o = 16; o; o >>= 1) m = fmaxf(m, __shfl_xor_sync(0xffffffffu, m, o));
        float e0 = __expf(v0 - m);
        float e1 = has1 ? __expf(v1 - m) : 0.f;
        float ssum = e0 + e1;
        #pragma unroll
        for (int o = 16; o; o >>= 1) ssum += __shfl_xor_sync(0xffffffffu, ssum, o);
        float inv = 1.0f / ssum;
        sc[lane] = e0 * inv;
        if (has1) sc[lane + 32] = e1 * inv;
    }
    __syncthreads();

    for (int u = tid; u < 1024; u += 512){
        float acc = 0.f;
        const float* er = eo + (long)b*50*1024 + u;
        #pragma unroll 10
        for (int s = 0; s < 50; s++)
            acc = fmaf(sc[s], er[(long)s*1024], acc);
        ctx[b*1024 + u] = acc;
    }
}

// ---------------- batched loss: one block per (t,b) row ----------------
__global__ __launch_bounds__(256) void loss_kernel(
    const float* __restrict__ logits, const int* __restrict__ targ, float* __restrict__ nll)
{
    __shared__ float red[256];
    const int r = blockIdx.x, tid = threadIdx.x;
    const int t = r >> 6, b = r & 63;
    const float* lr = logits + (long)r*16000;
    float m = -1e30f;
    for (int j = tid; j < 16000; j += 256) m = fmaxf(m, lr[j]);
    red[tid] = m; __syncthreads();
    for (int o = 128; o; o >>= 1){ if (tid < o) red[tid] = fmaxf(red[tid], red[tid+o]); __syncthreads(); }
    m = red[0]; __syncthreads();
    float s = 0.f;
    for (int j = tid; j < 16000; j += 256) s += __expf(lr[j] - m);
    red[tid] = s; __syncthreads();
    for (int o = 128; o; o >>= 1){ if (tid < o) red[tid] += red[tid+o]; __syncthreads(); }
    if (tid == 0){
        int yt = targ[b*50 + t + 1];
        float lse = m + __logf(red[0]);
        float v = (yt != 0) ? (lse - lr[yt]) * (1.0f/64.0f) : 0.f;
        nll[r] = v;
    }
}

__global__ __launch_bounds__(1024) void final_reduce(const float* __restrict__ nll, float* __restrict__ out){
    __shared__ float red[1024];
    int tid = threadIdx.x;
    float s = 0.f;
    for (int i = tid; i < 3136; i += 1024) s += nll[i];
    red[tid] = s; __syncthreads();
    for (int o = 512; o; o >>= 1){ if (tid < o) red[tid] += red[tid+o]; __syncthreads(); }
    if (tid == 0) out[0] = red[0];
}

// ---------------- host orchestration ----------------
extern "C" void kernel_launch(void* const* d_in, const int* in_sizes, int n_in,
                              void* d_out, int out_size) {
    const int*   inp     = (const int*)  d_in[0];
    const int*   targ    = (const int*)  d_in[1];
    const float* enc_hid = (const float*)d_in[2];
    const float* enc_emb = (const float*)d_in[3];
    const float* enc_Wx  = (const float*)d_in[4];
    const float* enc_Wh  = (const float*)d_in[5];
    const float* enc_b   = (const float*)d_in[6];
    const float* W1      = (const float*)d_in[7];
    const float* b1      = (const float*)d_in[8];
    const float* W2      = (const float*)d_in[9];
    const float* b2      = (const float*)d_in[10];
    const float* V       = (const float*)d_in[11];
    const float* bV      = (const float*)d_in[12];
    const float* dec_emb = (const float*)d_in[13];
    const float* dec_Wx  = (const float*)d_in[14];
    /* dec_Wh d_in[15] unused: decoder GRU h==0 */
    const float* dec_b   = (const float*)d_in[16];
    const float* fc_W    = (const float*)d_in[17];
    const float* fc_b    = (const float*)d_in[18];
    float* out = (float*)d_out;

    float* S = nullptr;  cudaGetSymbolAddress((void**)&S, g_scratch);
    int*   didx = nullptr; cudaGetSymbolAddress((void**)&didx, g_didx);

    float* encgi = S + O_ENCGI;
    float* dembgi= S + O_DEMB;
    float* eo    = S + O_EO;
    float* keys  = S + O_KEYS;
    float* part  = S + O_PART;
    float* qpart = S + O_QPART;
    float* h     = S + O_H;
    float* ctx   = S + O_CTX;
    float* hall  = S + O_HALL;
    float* logits= S + O_LOG;
    float* nll   = S + O_NLL;

    // setup
    setup_didx<<<13, 256>>>(targ, didx);
    copy_vec<<<256, 256>>>(h, enc_hid);

    // hoisted input-side GEMMs
    gemm_tile64<<<dim3(48, 50), 256>>>(enc_emb, 256, inp,  enc_Wx,               enc_b, encgi,  3072, 256);
    gemm_tile64<<<dim3(48, 49), 256>>>(dec_emb, 256, didx, dec_Wx + 1024L*3072,  dec_b, dembgi, 3072, 256);

    // encoder recurrence
    for (int t = 0; t < 50; t++){
        gemm_skinny<<<dim3(96, 4), 256>>>(h, enc_Wh, part, 3072, 1024, 4);
        enc_combine<<<256, 256>>>(t, encgi, part, h, eo, enc_b);
    }

    // keys = enc_out @ W2 + b2
    gemm_tile64<<<dim3(16, 50), 256>>>(eo, 1024, nullptr, W2, b2, keys, 1024, 1024);

    // decoder recurrence (h holds h_last from encoder = initial query state)
    for (int t = 0; t < 49; t++){
        gemm_skinny<<<dim3(32, 4), 256>>>(h, W1, qpart, 1024, 1024, 4);
        attention<<<64, 512>>>(qpart, keys, eo, ctx, b1, V, bV);
        gemm_skinny<<<dim3(96, 4), 256>>>(ctx, dec_Wx, part, 3072, 1024, 4);
        dec_combine<<<256, 256>>>(t, dembgi, part, h, hall, dec_b);
    }

    // batched logits GEMM (off the critical path): 3136 x 16000, K=1024
    gemm_tile64<<<dim3(250, 49), 256>>>(hall, 1024, nullptr, fc_W, fc_b, logits, 16000, 1024);

    // batched loss + deterministic final reduce
    loss_kernel<<<3136, 256>>>(logits, targ, nll);
    final_reduce<<<1, 1024>>>(nll, out);
}

// round 3
// speedup vs baseline: 3.0615x; 3.0615x over previous
#include <cuda_runtime.h>
#include <cuda_bf16.h>
#include <cstdint>

typedef unsigned long long ull;
#define DEV __device__ __forceinline__

DEV ull pk2(float lo, float hi){
    unsigned a = __float_as_uint(lo), b = __float_as_uint(hi);
    ull r; asm("mov.b64 %0, {%1, %2};" : "=l"(r) : "r"(a), "r"(b)); return r;
}
DEV void fma2(ull& d, ull a, ull b){
    asm("fma.rn.f32x2 %0, %1, %2, %0;" : "+l"(d) : "l"(a), "l"(b));
}
DEV float2 up2(ull v){
    unsigned a, b; asm("mov.b64 {%0, %1}, %2;" : "=r"(a), "=r"(b) : "l"(v));
    return make_float2(__uint_as_float(a), __uint_as_float(b));
}
DEV float sigm(float x){ return 1.0f/(1.0f+__expf(-x)); }
DEV float ftanh(float x){ return 1.0f - 2.0f/(__expf(2.0f*x)+1.0f); }
DEV float tanha(float x){ float r; asm("tanh.approx.f32 %0, %1;" : "=f"(r) : "f"(x)); return r; }
DEV unsigned swz(unsigned off){ return off ^ ((off>>3)&0x70); }

// ---------------- dims: B=64,S=50,T=50,U=1024,E=256,VT=16000,G3=3072 ----------------

// ---------------- f32 scratch ----------------
constexpr long O_ENCGI = 0;                         // 3200x3072
constexpr long O_DEMB  = O_ENCGI + 9830400L;        // 3136x3072
constexpr long O_EO    = O_DEMB  + 9633792L;        // 3200x1024
constexpr long O_KEYS  = O_EO    + 3276800L;        // 3200x1024
constexpr long O_PART  = O_KEYS  + 3276800L;        // 64x3072
constexpr long O_QPART = O_PART  + 196608L;         // 64x1024
constexpr long O_H     = O_QPART + 65536L;          // 64x1024 (f32 recurrence state)
constexpr long O_SC    = O_H     + 65536L;          // 64x64 raw scores
constexpr long O_LOG   = O_SC    + 4096L;           // 3136x16000
constexpr long O_NLL   = O_LOG   + 50176000L;       // 3136
constexpr long SCRATCH_TOTAL = O_NLL + 3200L;

__device__ __align__(16) float g_scratch[SCRATCH_TOTAL];
__device__ int g_didx[3136];

// bf16 buffers
__device__ __align__(16) __nv_bfloat16 g_fcWb[16384000];   // 1024x16000
__device__ __align__(16) __nv_bfloat16 g_encWhb[3145728];  // 1024x3072
__device__ __align__(16) __nv_bfloat16 g_W1b[1048576];     // 1024x1024
__device__ __align__(16) __nv_bfloat16 g_decWxb[3145728];  // rows 0..1023 of dec_Wx
__device__ __align__(16) __nv_bfloat16 g_hb[65536];
__device__ __align__(16) __nv_bfloat16 g_ctxb[65536];
__device__ __align__(16) __nv_bfloat16 g_hallb[3211264];   // 3136x1024

// ---------------- small setup ----------------
__global__ void setup_didx(const int* __restrict__ targ, int* __restrict__ gd){
    int i = blockIdx.x*256 + threadIdx.x;
    if (i < 3136){ int t = i >> 6, b = i & 63; gd[i] = targ[b*50 + t]; }
}
__global__ void init_h(float* __restrict__ h, __nv_bfloat16* __restrict__ hb,
                       const float* __restrict__ src){
    int i = blockIdx.x*256 + threadIdx.x;
    float v = src[i]; h[i] = v; hb[i] = __float2bfloat16(v);
}
__global__ void cvt_bf16(__nv_bfloat16* __restrict__ dst, const float* __restrict__ src, long n){
    long i = ((long)blockIdx.x*256 + threadIdx.x)*4;
    if (i < n){
        float4 v = *reinterpret_cast<const float4*>(src + i);
        __nv_bfloat162 lo = __floats2bfloat162_rn(v.x, v.y);
        __nv_bfloat162 hi = __floats2bfloat162_rn(v.z, v.w);
        uint2 o; o.x = *reinterpret_cast<unsigned*>(&lo); o.y = *reinterpret_cast<unsigned*>(&hi);
        *reinterpret_cast<uint2*>(dst + i) = o;
    }
}

// ---------------- f32 64x64-tile GEMM with gather (hoisted input GEMMs, keys) ----------------
__global__ __launch_bounds__(256) void gemm_tile64(
    const float* __restrict__ A, int lda, const int* __restrict__ gidx,
    const float* __restrict__ Bm, const float* __restrict__ bias,
    float* __restrict__ C, int N, int K)
{
    __shared__ __align__(16) ull   As2[16][68];
    __shared__ __align__(16) float Bs[16][64];
    const int tid = threadIdx.x;
    const int tx = tid & 15, ty = tid >> 4;
    const int row0 = blockIdx.y << 6, col0 = blockIdx.x << 6;

    ull acc[4][2];
    #pragma unroll
    for (int i=0;i<4;i++){ acc[i][0]=0ull; acc[i][1]=0ull; }

    const int ra = tid >> 2, qa = tid & 3;
    long arow = gidx ? (long)gidx[row0 + ra] : (long)(row0 + ra);
    const int kb = tid >> 4, c4 = tid & 15;

    for (int k0 = 0; k0 < K; k0 += 16){
        float4 av = *reinterpret_cast<const float4*>(&A[arow*lda + k0 + (qa<<2)]);
        int kk = qa << 2;
        As2[kk+0][ra] = pk2(av.x, av.x);
        As2[kk+1][ra] = pk2(av.y, av.y);
        As2[kk+2][ra] = pk2(av.z, av.z);
        As2[kk+3][ra] = pk2(av.w, av.w);
        *reinterpret_cast<float4*>(&Bs[kb][c4<<2]) =
            *reinterpret_cast<const float4*>(&Bm[(long)(k0+kb)*N + col0 + (c4<<2)]);
        __syncthreads();
        #pragma unroll
        for (int k=0;k<16;k++){
            ulonglong2 a01 = *reinterpret_cast<const ulonglong2*>(&As2[k][ty<<2]);
            ulonglong2 a23 = *reinterpret_cast<const ulonglong2*>(&As2[k][(ty<<2)+2]);
            ulonglong2 bb  = *reinterpret_cast<const ulonglong2*>(&Bs[k][tx<<2]);
            fma2(acc[0][0], a01.x, bb.x); fma2(acc[0][1], a01.x, bb.y);
            fma2(acc[1][0], a01.y, bb.x); fma2(acc[1][1], a01.y, bb.y);
            fma2(acc[2][0], a23.x, bb.x); fma2(acc[2][1], a23.x, bb.y);
            fma2(acc[3][0], a23.y, bb.x); fma2(acc[3][1], a23.y, bb.y);
        }
        __syncthreads();
    }
    const int c0 = col0 + (tx<<2);
    float4 bv = make_float4(0.f,0.f,0.f,0.f);
    if (bias) bv = *reinterpret_cast<const float4*>(&bias[c0]);
    #pragma unroll
    for (int i=0;i<4;i++){
        int r = row0 + (ty<<2) + i;
        float2 p0 = up2(acc[i][0]), p1 = up2(acc[i][1]);
        float4 o = make_float4(p0.x+bv.x, p0.y+bv.y, p1.x+bv.z, p1.y+bv.w);
        *reinterpret_cast<float4*>(&C[(long)r*N + c0]) = o;
    }
}

// ---------------- bf16 tensor-core GEMM: C(f32) = A(bf16) @ B(bf16) + bias ----------------
// BM=64, BN=64, BK=64, 256 threads (8 warps: 2x4). M,N,K multiples of 64.
__global__ __launch_bounds__(256) void gemm_mma(
    const __nv_bfloat16* __restrict__ A, int lda,
    const __nv_bfloat16* __restrict__ Bm, int ldb,
    const float* __restrict__ bias,
    float* __restrict__ C, int ldc, int K)
{
    __shared__ __align__(16) char smA[2][8192];
    __shared__ __align__(16) char smB[2][8192];
    const int tid = threadIdx.x;
    const int warp = tid >> 5, lane = tid & 31;
    const int wm = warp >> 2, wn = warp & 3;      // warp tile: rows wm*32..+32, cols wn*16..+16
    const int row0 = blockIdx.y << 6, col0 = blockIdx.x << 6;

    unsigned sA[2] = { (unsigned)__cvta_generic_to_shared(smA[0]),
                       (unsigned)__cvta_generic_to_shared(smA[1]) };
    unsigned sB[2] = { (unsigned)__cvta_generic_to_shared(smB[0]),
                       (unsigned)__cvta_generic_to_shared(smB[1]) };

    float acc[2][2][4];
    #pragma unroll
    for (int mt=0;mt<2;mt++)
        #pragma unroll
        for (int nt=0;nt<2;nt++)
            #pragma unroll
            for (int q=0;q<4;q++) acc[mt][nt][q] = 0.f;

    const int lr = tid >> 3, lc = tid & 7;        // loader: 32 rows x 8 chunks; x2 => 64 rows

    auto issue = [&](int st, int k0){
        #pragma unroll
        for (int i=0;i<2;i++){
            int r = lr + i*32;
            const void* gA = (const void*)(A + (long)(row0 + r)*lda + k0 + lc*8);
            unsigned dA = sA[st] + swz(r*128 + lc*16);
            asm volatile("cp.async.cg.shared.global [%0], [%1], 16;" :: "r"(dA), "l"(gA));
            const void* gB = (const void*)(Bm + (long)(k0 + r)*ldb + col0 + lc*8);
            unsigned dB = sB[st] + swz(r*128 + lc*16);
            asm volatile("cp.async.cg.shared.global [%0], [%1], 16;" :: "r"(dB), "l"(gB));
        }
        asm volatile("cp.async.commit_group;");
    };

    const int nk = K >> 6;
    issue(0, 0);
    for (int kt = 0; kt < nk; kt++){
        if (kt + 1 < nk){
            issue((kt+1)&1, (kt+1)<<6);
            asm volatile("cp.async.wait_group 1;" ::: "memory");
        } else {
            asm volatile("cp.async.wait_group 0;" ::: "memory");
        }
        __syncthreads();
        const int st = kt & 1;
        #pragma unroll
        for (int ks = 0; ks < 4; ks++){
            unsigned a[2][4];
            #pragma unroll
            for (int mt = 0; mt < 2; mt++){
                int r = wm*32 + mt*16 + (lane & 15);
                int c = ks*16 + (lane >> 4)*8;
                unsigned addr = sA[st] + swz(r*128 + c*2);
                asm volatile("ldmatrix.sync.aligned.m8n8.x4.shared.b16 {%0,%1,%2,%3}, [%4];"
                    : "=r"(a[mt][0]),"=r"(a[mt][1]),"=r"(a[mt][2]),"=r"(a[mt][3]) : "r"(addr));
            }
            unsigned b[4];
            {
                int kk = ks*16 + ((lane>>3)&1)*8 + (lane & 7);
                int nn = wn*16 + (lane>>4)*8;
                unsigned addr = sB[st] + swz(kk*128 + nn*2);
                asm volatile("ldmatrix.sync.aligned.m8n8.x4.trans.shared.b16 {%0,%1,%2,%3}, [%4];"
                    : "=r"(b[0]),"=r"(b[1]),"=r"(b[2]),"=r"(b[3]) : "r"(addr));
            }
            #pragma unroll
            for (int mt = 0; mt < 2; mt++)
                #pragma unroll
                for (int nt = 0; nt < 2; nt++){
                    float* d = acc[mt][nt];
                    asm volatile("mma.sync.aligned.m16n8k16.row.col.f32.bf16.bf16.f32 "
                        "{%0,%1,%2,%3}, {%4,%5,%6,%7}, {%8,%9}, {%0,%1,%2,%3};"
                        : "+f"(d[0]),"+f"(d[1]),"+f"(d[2]),"+f"(d[3])
                        : "r"(a[mt][0]),"r"(a[mt][1]),"r"(a[mt][2]),"r"(a[mt][3]),
                          "r"(b[nt*2]),"r"(b[nt*2+1]));
                }
        }
        __syncthreads();
    }

    const int rb = row0 + wm*32 + (lane>>2);
    const int cb = col0 + wn*16 + (lane&3)*2;
    #pragma unroll
    for (int nt = 0; nt < 2; nt++){
        int cc = cb + nt*8;
        float bv0 = bias ? bias[cc] : 0.f, bv1 = bias ? bias[cc+1] : 0.f;
        #pragma unroll
        for (int mt = 0; mt < 2; mt++){
            int r = rb + mt*16;
            *reinterpret_cast<float2*>(&C[(long)r*ldc + cc]) =
                make_float2(acc[mt][nt][0]+bv0, acc[mt][nt][1]+bv1);
            *reinterpret_cast<float2*>(&C[(long)(r+8)*ldc + cc]) =
                make_float2(acc[mt][nt][2]+bv0, acc[mt][nt][3]+bv1);
        }
    }
}

// ---------------- encoder GRU combine (single partial) ----------------
__global__ __launch_bounds__(256) void enc_combine(
    int t, const float* __restrict__ encgi, const float* __restrict__ part,
    float* __restrict__ h, __nv_bfloat16* __restrict__ hb,
    float* __restrict__ eo, const float* __restrict__ encb)
{
    int i = blockIdx.x*256 + threadIdx.x;
    int b = i >> 10, u = i & 1023;
    long gb = (long)(b*50 + t)*3072;
    long p  = (long)b*3072;
    float giz = encgi[gb + u];
    float gir = encgi[gb + 1024 + u];
    float gih = encgi[gb + 2048 + u];
    float ghz = part[p+u]      + encb[3072 + u];
    float ghr = part[p+1024+u] + encb[3072 + 1024 + u];
    float ghh = part[p+2048+u] + encb[3072 + 2048 + u];
    float z = sigm(giz + ghz);
    float r = sigm(gir + ghr);
    float hc = ftanh(gih + r*ghh);
    float hn = z*h[i] + (1.0f - z)*hc;
    h[i] = hn;
    hb[i] = __float2bfloat16(hn);
    eo[(long)(b*50 + t)*1024 + u] = hn;
}

// ---------------- decoder GRU combine (h==0 path) ----------------
__global__ __launch_bounds__(256) void dec_combine(
    int t, const float* __restrict__ dembgi, const float* __restrict__ part,
    __nv_bfloat16* __restrict__ hb, __nv_bfloat16* __restrict__ hallb,
    const float* __restrict__ decb)
{
    int i = blockIdx.x*256 + threadIdx.x;
    int b = i >> 10, u = i & 1023;
    long db = (long)(t*64 + b)*3072;
    long p  = (long)b*3072;
    float giz = dembgi[db + u]        + part[p+u];
    float gir = dembgi[db + 1024 + u] + part[p+1024+u];
    float gih = dembgi[db + 2048 + u] + part[p+2048+u];
    float z = sigm(giz + decb[3072 + u]);
    float r = sigm(gir + decb[3072 + 1024 + u]);
    float hc = ftanh(gih + r*decb[3072 + 2048 + u]);
    float hn = (1.0f - z)*hc;
    __nv_bfloat16 hv = __float2bfloat16(hn);
    hb[i] = hv;
    hallb[(long)(t*64 + b)*1024 + u] = hv;
}

// ---------------- attention scores (grid 64 x 2; MUFU-heavy) ----------------
__global__ __launch_bounds__(256) void attn_score(
    const float* __restrict__ qpart, const float* __restrict__ keys,
    float* __restrict__ gsc, const float* __restrict__ b1,
    const float* __restrict__ V, const float* __restrict__ bV)
{
    __shared__ float qs[1024];
    const int b = blockIdx.x, sh = blockIdx.y;
    const int tid = threadIdx.x;
    for (int u = tid; u < 1024; u += 256)
        qs[u] = qpart[b*1024 + u] + b1[u];
    __syncthreads();
    const int w = tid >> 5, lane = tid & 31;
    for (int s = sh*25 + w; s < sh*25 + 25; s += 8){
        const float* kr = keys + (long)(b*50 + s)*1024;
        float acc = 0.f;
        for (int u = lane; u < 1024; u += 32)
            acc += V[u] * tanha(qs[u] + kr[u]);
        #pragma unroll
        for (int o = 16; o; o >>= 1) acc += __shfl_xor_sync(0xffffffffu, acc, o);
        if (lane == 0) gsc[b*64 + s] = acc + bV[0];
    }
}

// ---------------- softmax + context (grid 64) ----------------
__global__ __launch_bounds__(512) void attn_ctx(
    const float* __restrict__ gsc, const float* __restrict__ eo,
    __nv_bfloat16* __restrict__ ctxb)
{
    __shared__ float sc[64];
    const int b = blockIdx.x, tid = threadIdx.x;
    if (tid < 64) sc[tid] = (tid < 50) ? gsc[b*64 + tid] : -1e30f;
    __syncthreads();
    if (tid < 32){
        float v0 = sc[tid], v1 = sc[tid + 32];
        float m = fmaxf(v0, v1);
        #pragma unroll
        for (int o = 16; o; o >>= 1) m = fmaxf(m, __shfl_xor_sync(0xffffffffu, m, o));
        float e0 = __expf(v0 - m);
        float e1 = (tid + 32 < 50) ? __expf(v1 - m) : 0.f;
        float ssum = e0 + e1;
        #pragma unroll
        for (int o = 16; o; o >>= 1) ssum += __shfl_xor_sync(0xffffffffu, ssum, o);
        float inv = 1.0f / ssum;
        sc[tid] = e0 * inv;
        sc[tid + 32] = e1 * inv;
    }
    __syncthreads();
    for (int u = tid; u < 1024; u += 512){
        float acc = 0.f;
        const float* er = eo + (long)b*51200 + u;
        #pragma unroll 10
        for (int s = 0; s < 50; s++)
            acc = fmaf(sc[s], er[(long)s*1024], acc);
        ctxb[b*1024 + u] = __float2bfloat16(acc);
    }
}

// ---------------- batched loss ----------------
__global__ __launch_bounds__(256) void loss_kernel(
    const float* __restrict__ logits, const int* __restrict__ targ, float* __restrict__ nll)
{
    __shared__ float red[256];
    const int r = blockIdx.x, tid = threadIdx.x;
    const int t = r >> 6, b = r & 63;
    const float* lr = logits + (long)r*16000;
    float m = -1e30f;
    for (int j = tid; j < 16000; j += 256) m = fmaxf(m, lr[j]);
    red[tid] = m; __syncthreads();
    for (int o = 128; o; o >>= 1){ if (tid < o) red[tid] = fmaxf(red[tid], red[tid+o]); __syncthreads(); }
    m = red[0]; __syncthreads();
    float s = 0.f;
    for (int j = tid; j < 16000; j += 256) s += __expf(lr[j] - m);
    red[tid] = s; __syncthreads();
    for (int o = 128; o; o >>= 1){ if (tid < o) red[tid] += red[tid+o]; __syncthreads(); }
    if (tid == 0){
        int yt = targ[b*50 + t + 1];
        float lse = m + __logf(red[0]);
        nll[r] = (yt != 0) ? (lse - lr[yt]) * (1.0f/64.0f) : 0.f;
    }
}

__global__ __launch_bounds__(1024) void final_reduce(const float* __restrict__ nll, float* __restrict__ out){
    __shared__ float red[1024];
    int tid = threadIdx.x;
    float s = 0.f;
    for (int i = tid; i < 3136; i += 1024) s += nll[i];
    red[tid] = s; __syncthreads();
    for (int o = 512; o; o >>= 1){ if (tid < o) red[tid] += red[tid+o]; __syncthreads(); }
    if (tid == 0) out[0] = red[0];
}

// ---------------- host orchestration ----------------
extern "C" void kernel_launch(void* const* d_in, const int* in_sizes, int n_in,
                              void* d_out, int out_size) {
    const int*   inp     = (const int*)  d_in[0];
    const int*   targ    = (const int*)  d_in[1];
    const float* enc_hid = (const float*)d_in[2];
    const float* enc_emb = (const float*)d_in[3];
    const float* enc_Wx  = (const float*)d_in[4];
    const float* enc_Wh  = (const float*)d_in[5];
    const float* enc_b   = (const float*)d_in[6];
    const float* W1      = (const float*)d_in[7];
    const float* b1      = (const float*)d_in[8];
    const float* W2      = (const float*)d_in[9];
    const float* b2      = (const float*)d_in[10];
    const float* V       = (const float*)d_in[11];
    const float* bV      = (const float*)d_in[12];
    const float* dec_emb = (const float*)d_in[13];
    const float* dec_Wx  = (const float*)d_in[14];
    const float* dec_b   = (const float*)d_in[16];
    const float* fc_W    = (const float*)d_in[17];
    const float* fc_b    = (const float*)d_in[18];
    float* out = (float*)d_out;

    float* S = nullptr;  cudaGetSymbolAddress((void**)&S, g_scratch);
    int*   didx = nullptr; cudaGetSymbolAddress((void**)&didx, g_didx);
    __nv_bfloat16 *fcWb, *encWhb, *W1b, *decWxb, *hb, *ctxb, *hallb;
    cudaGetSymbolAddress((void**)&fcWb,   g_fcWb);
    cudaGetSymbolAddress((void**)&encWhb, g_encWhb);
    cudaGetSymbolAddress((void**)&W1b,    g_W1b);
    cudaGetSymbolAddress((void**)&decWxb, g_decWxb);
    cudaGetSymbolAddress((void**)&hb,     g_hb);
    cudaGetSymbolAddress((void**)&ctxb,   g_ctxb);
    cudaGetSymbolAddress((void**)&hallb,  g_hallb);

    float* encgi = S + O_ENCGI;
    float* dembgi= S + O_DEMB;
    float* eo    = S + O_EO;
    float* keys  = S + O_KEYS;
    float* part  = S + O_PART;
    float* qpart = S + O_QPART;
    float* h     = S + O_H;
    float* gsc   = S + O_SC;
    float* logits= S + O_LOG;
    float* nll   = S + O_NLL;

    // setup + weight conversions
    setup_didx<<<13, 256>>>(targ, didx);
    init_h<<<256, 256>>>(h, hb, enc_hid);
    cvt_bf16<<<16000, 256>>>(fcWb,   fc_W,   16384000L);
    cvt_bf16<<<3072, 256>>>(encWhb, enc_Wh, 3145728L);
    cvt_bf16<<<1024, 256>>>(W1b,    W1,     1048576L);
    cvt_bf16<<<3072, 256>>>(decWxb, dec_Wx, 3145728L);   // first 1024 rows (ctx slice)

    // hoisted input-side GEMMs (f32, with gather)
    gemm_tile64<<<dim3(48, 50), 256>>>(enc_emb, 256, inp,  enc_Wx,              enc_b, encgi,  3072, 256);
    gemm_tile64<<<dim3(48, 49), 256>>>(dec_emb, 256, didx, dec_Wx + 1024L*3072, dec_b, dembgi, 3072, 256);

    // encoder recurrence
    for (int t = 0; t < 50; t++){
        gemm_mma<<<dim3(48, 1), 256>>>(hb, 1024, encWhb, 3072, nullptr, part, 3072, 1024);
        enc_combine<<<256, 256>>>(t, encgi, part, h, hb, eo, enc_b);
    }

    // keys = enc_out @ W2 + b2 (f32)
    gemm_tile64<<<dim3(16, 50), 256>>>(eo, 1024, nullptr, W2, b2, keys, 1024, 1024);

    // decoder recurrence
    for (int t = 0; t < 49; t++){
        gemm_mma<<<dim3(16, 1), 256>>>(hb, 1024, W1b, 1024, nullptr, qpart, 1024, 1024);
        attn_score<<<dim3(64, 2), 256>>>(qpart, keys, gsc, b1, V, bV);
        attn_ctx<<<64, 512>>>(gsc, eo, ctxb);
        gemm_mma<<<dim3(48, 1), 256>>>(ctxb, 1024, decWxb, 3072, nullptr, part, 3072, 1024);
        dec_combine<<<256, 256>>>(t, dembgi, part, hb, hallb, dec_b);
    }

    // batched fc logits GEMM (tensor cores)
    gemm_mma<<<dim3(250, 49), 256>>>(hallb, 1024, fcWb, 16000, fc_b, logits, 16000, 1024);

    // loss
    loss_kernel<<<3136, 256>>>(logits, targ, nll);
    final_reduce<<<1, 1024>>>(nll, out);
}